// round 4
// baseline (speedup 1.0000x reference)
#include <cuda_runtime.h>

// Problem constants (fixed by the reference)
#define SEQ_LEN   512
#define EMB       768
#define NLAB      9
#define FEAT      2354            // 3*768 + 50
#define WDIM      50
#define MAXW      16
#define NSPANS    32768
#define HALF_K    384             // EMB/2, staged per smem pass
#define NBLK      148
#define NTHR      512

// Packed tables (allocation-free rule: __device__ globals)
// g_S[t*9+l] = (Ps[t][l], Pc[t][l])   Pc[t] = sum of tokens [0,t)
// g_E[t*9+l] = (Pe[t][l], Pc[t][l])
// g_Wb[w*9+l] = (width_proj+bias, 1/w)
__device__ float2 g_S[SEQ_LEN * NLAB];
__device__ float2 g_E[SEQ_LEN * NLAB];
__device__ float  g_Pa[SEQ_LEN * NLAB];
__device__ float2 g_Wb[(MAXW + 1) * NLAB];

// Grid barrier state (generation counter is monotonic -> replay-safe)
__device__ unsigned g_count = 0;
__device__ volatile unsigned g_gen = 0;

__device__ __forceinline__ void grid_barrier() {
    __threadfence();                     // publish this thread's writes
    __syncthreads();
    if (threadIdx.x == 0) {
        unsigned gen = g_gen;
        if (atomicAdd(&g_count, 1) == gridDim.x - 1) {
            atomicExch(&g_count, 0);
            __threadfence();
            g_gen = gen + 1;             // release
        } else {
            while (g_gen == gen) __nanosleep(64);
        }
    }
    __syncthreads();
    __threadfence();                     // acquire
}

__global__ void __launch_bounds__(NTHR, 1)
fused_kernel(const float* __restrict__ seq,
             const int*   __restrict__ st,
             const int*   __restrict__ en,
             const int*   __restrict__ wd,
             const float* __restrict__ wt,
             const float* __restrict__ W,
             const float* __restrict__ b,
             float* __restrict__ out) {
    __shared__ __align__(16) float sw[27 * HALF_K];   // 41.5 KB

    const int tid  = threadIdx.x;
    const int bid  = blockIdx.x;
    const int warp = tid >> 5;
    const int lane = tid & 31;

    // ============ Phase 1: token projections (blocks 0..63) ============
    // 64 blocks x 4 compute-warps x 2 tokens = 512 tokens.
    if (bid < 64) {
        float a0[27], a1[27];
        #pragma unroll
        for (int j = 0; j < 27; j++) { a0[j] = 0.f; a1[j] = 0.f; }
        const int tp = (bid * 4 + warp) * 2;          // valid for warp<4

        #pragma unroll
        for (int c = 0; c < 2; c++) {
            // Stage 27 x 384-float W half-chunk (float2: rows 8B-aligned)
            for (int i = tid; i < 27 * (HALF_K / 2); i += NTHR) {
                const int j = i / (HALF_K / 2);
                const int p = (i % (HALF_K / 2)) * 2;
                const int l = j % 9, sl = j / 9;
                const float2 v = __ldg(reinterpret_cast<const float2*>(
                    W + (size_t)l * FEAT + sl * EMB + c * HALF_K + p));
                sw[j * HALF_K + p]     = v.x;
                sw[j * HALF_K + p + 1] = v.y;
            }
            __syncthreads();

            if (warp < 4) {
                #pragma unroll
                for (int it = 0; it < 3; it++) {
                    const int kk = c * HALF_K + it * 128 + lane * 4;
                    const float4 s0 = *reinterpret_cast<const float4*>(
                        seq + (size_t)tp * EMB + kk);
                    const float4 s1 = *reinterpret_cast<const float4*>(
                        seq + (size_t)(tp + 1) * EMB + kk);
                    #pragma unroll
                    for (int j = 0; j < 27; j++) {
                        const float4 w4 = *reinterpret_cast<const float4*>(
                            sw + j * HALF_K + it * 128 + lane * 4);
                        a0[j] += s0.x * w4.x + s0.y * w4.y + s0.z * w4.z + s0.w * w4.w;
                        a1[j] += s1.x * w4.x + s1.y * w4.y + s1.z * w4.z + s1.w * w4.w;
                    }
                }
            }
            __syncthreads();
        }

        if (warp < 4) {
            #pragma unroll
            for (int j = 0; j < 27; j++) {
                float v0 = a0[j], v1 = a1[j];
                #pragma unroll
                for (int o = 16; o > 0; o >>= 1) {
                    v0 += __shfl_down_sync(0xffffffffu, v0, o);
                    v1 += __shfl_down_sync(0xffffffffu, v1, o);
                }
                if (lane == 0) {
                    const int l = j % 9, sl = j / 9;
                    if (sl == 0) {
                        reinterpret_cast<float*>(g_S)[(tp * 9 + l) * 2] = v0;
                        reinterpret_cast<float*>(g_S)[((tp + 1) * 9 + l) * 2] = v1;
                    } else if (sl == 1) {
                        reinterpret_cast<float*>(g_E)[(tp * 9 + l) * 2] = v0;
                        reinterpret_cast<float*>(g_E)[((tp + 1) * 9 + l) * 2] = v1;
                    } else {
                        g_Pa[tp * 9 + l] = v0;
                        g_Pa[(tp + 1) * 9 + l] = v1;
                    }
                }
            }
        }
    }

    grid_barrier();

    // ============ Phase 2a: block 0 -> 9 parallel scans over 512 tokens ====
    if (bid == 0) {
        float* tot   = sw;                 // reuse smem: [16][9]
        float* carry = sw + 16 * NLAB;     // [16][9]

        float x[NLAB], a[NLAB];
        #pragma unroll
        for (int l = 0; l < NLAB; l++) { x[l] = g_Pa[tid * NLAB + l]; a[l] = x[l]; }

        #pragma unroll
        for (int l = 0; l < NLAB; l++) {
            #pragma unroll
            for (int o = 1; o < 32; o <<= 1) {
                const float y = __shfl_up_sync(0xffffffffu, a[l], o);
                if (lane >= o) a[l] += y;
            }
        }
        if (lane == 31) {
            #pragma unroll
            for (int l = 0; l < NLAB; l++) tot[warp * NLAB + l] = a[l];
        }
        __syncthreads();
        if (tid < NLAB) {
            float r = 0.f;
            #pragma unroll
            for (int w = 0; w < 16; w++) {
                carry[w * NLAB + tid] = r;
                r += tot[w * NLAB + tid];
            }
        }
        __syncthreads();
        #pragma unroll
        for (int l = 0; l < NLAB; l++) {
            // exclusive prefix for token tid = incl - own
            const float excl = a[l] - x[l] + carry[warp * NLAB + l];
            reinterpret_cast<float*>(g_S)[(tid * NLAB + l) * 2 + 1] = excl;
            reinterpret_cast<float*>(g_E)[(tid * NLAB + l) * 2 + 1] = excl;
        }
    }

    // ============ Phase 2b: block 1 -> width projection + reciprocals =====
    if (bid == 1 && tid < (MAXW + 1) * NLAB) {
        const int w = tid / NLAB;
        const int l = tid % NLAB;
        const float* wrow = W + (size_t)l * FEAT + 3 * EMB;
        float acc = __ldg(b + l);
        #pragma unroll
        for (int k = 0; k < WDIM; k++)
            acc += __ldg(wt + w * WDIM + k) * __ldg(wrow + k);
        g_Wb[tid] = make_float2(acc, 1.0f / (float)w);   // w=0 entry never read
    }

    grid_barrier();

    // ============ Phase 3: assemble logits (all blocks) ===================
    const int stride = NBLK * NTHR;            // 75776
    int m = bid * NTHR + tid;
    #pragma unroll
    for (int i = 0; i < 4; i++, m += stride) {
        if (m < NSPANS * NLAB) {
            const int span = m / NLAB;
            const int l    = m - span * NLAB;
            const int s = __ldg(st + span);
            const int e = __ldg(en + span);
            const int w = __ldg(wd + span);
            const float2 fs = g_S[s * NLAB + l];
            const float2 fe = g_E[e * NLAB + l];
            const float2 fw = g_Wb[w * NLAB + l];
            out[m] = fs.x + fe.x + (fe.y - fs.y) * fw.y + fw.x;
        }
    }
}

// ---------------------------------------------------------------------------
extern "C" void kernel_launch(void* const* d_in, const int* in_sizes, int n_in,
                              void* d_out, int out_size) {
    const float* seq = (const float*)d_in[0];   // [1,512,768]
    const int*   st  = (const int*)  d_in[1];   // [32768]
    const int*   en  = (const int*)  d_in[2];   // [32768]
    const int*   wd  = (const int*)  d_in[3];   // [32768]
    const float* wt  = (const float*)d_in[4];   // [17,50]
    const float* W   = (const float*)d_in[5];   // [9,2354]
    const float* b   = (const float*)d_in[6];   // [9]
    float* out = (float*)d_out;                 // [32768,9]

    fused_kernel<<<NBLK, NTHR>>>(seq, st, en, wd, wt, W, b, out);
}